// round 9
// baseline (speedup 1.0000x reference)
#include <cuda_runtime.h>
#include <math.h>

#define NMAX 20000
#define EMAX 320000
#define CDIM 64
#define NLMD 9
#define NBES 8
#define ZDIM 10

// ---------------- scratch (device globals; no allocation) ----------------
__device__ float g_msg[NMAX * NLMD * CDIM];   // [N][lm][c]  46.08 MB
__device__ float g_htable[ZDIM * CDIM];
__device__ float g_xout[NMAX * CDIM];
__device__ float g_U3s[NLMD * 45 * 4];        // symmetrized U3: [i][pair][p]
__device__ float g_U2s[45 * 4];               // symmetrized U2: [pair][p]
__device__ float g_Yb[EMAX * NLMD];           // per-edge spherical harmonics

// ---------------- zero the message buffer ----------------
__global__ void zero_msg_kernel(int n4) {
  int i = blockIdx.x * blockDim.x + threadIdx.x;
  float4* p = reinterpret_cast<float4*>(g_msg);
  if (i < n4) p[i] = make_float4(0.f, 0.f, 0.f, 0.f);
}

// ---------------- species embedding table ----------------
__global__ void htable_kernel(const float* __restrict__ W_embed,
                              const float* __restrict__ W_up) {
  int t = threadIdx.x;
  if (t < ZDIM * CDIM) {
    int z = t >> 6, c = t & 63;
    float acc = 0.f;
    #pragma unroll 8
    for (int k = 0; k < CDIM; k++)
      acc = fmaf(W_embed[z * CDIM + k], W_up[k * CDIM + c], acc);
    g_htable[t] = acc * (1.0f / (3.16227766016838f * 8.0f));  // /(sqrt(10)*sqrt(64))
  }
}

// ---------------- symmetrize U3/U2 over (j,k) ----------------
__global__ void symU_kernel(const float* __restrict__ U3,
                            const float* __restrict__ U2) {
  int t = blockIdx.x * blockDim.x + threadIdx.x;
  if (t >= 9 * 45) return;
  int i = t / 45, pr = t % 45;
  int j = 0, k = 0, acc = 0;
  for (int jj = 0; jj < 9; jj++) {
    int cnt = 9 - jj;
    if (pr < acc + cnt) { j = jj; k = jj + (pr - acc); break; }
    acc += cnt;
  }
  #pragma unroll
  for (int p = 0; p < 4; p++) {
    float v = U3[((i * 9 + j) * 9 + k) * 4 + p];
    if (j != k) v += U3[((i * 9 + k) * 9 + j) * 4 + p];
    g_U3s[(i * 45 + pr) * 4 + p] = v;
  }
  if (i == 0) {
    #pragma unroll
    for (int p = 0; p < 4; p++) {
      float v = U2[(j * 9 + k) * 4 + p];
      if (j != k) v += U2[(k * 9 + j) * 4 + p];
      g_U2s[pr * 4 + p] = v;
    }
  }
}

// ---------------- fused edge kernel (3 blocks/SM, B via LDG/L1) ----------
struct ESmem3 {
  float Fa[128 * 68];      // activation ping (34.8 KB)
  float Fb[128 * 68];      // activation pong; EF (stride 9) overlaid at start
  float htab[ZDIM * CDIM]; // 2.5 KB
  int   recv[128];
  int   zs[128];
};                         // 73216 B total -> 3 blocks/SM

// Scalar-A GEMM (layer 1; A stride 9 not 16B-aligned). B from GLOBAL (LDG).
template <int K, bool ACT>
__device__ __forceinline__ void gemm128(const float* __restrict__ A, int As,
                                        const float* __restrict__ B, int Bs,
                                        float* __restrict__ Cm, int tid) {
  int rg = tid >> 4, cg = tid & 15;
  float acc[8][4];
  #pragma unroll
  for (int i = 0; i < 8; i++) { acc[i][0] = 0.f; acc[i][1] = 0.f; acc[i][2] = 0.f; acc[i][3] = 0.f; }
  #pragma unroll 4
  for (int k = 0; k < K; k++) {
    float4 b = *reinterpret_cast<const float4*>(B + k * Bs + cg * 4);
    #pragma unroll
    for (int i = 0; i < 8; i++) {
      float a = A[(rg + 16 * i) * As + k];
      acc[i][0] = fmaf(a, b.x, acc[i][0]);
      acc[i][1] = fmaf(a, b.y, acc[i][1]);
      acc[i][2] = fmaf(a, b.z, acc[i][2]);
      acc[i][3] = fmaf(a, b.w, acc[i][3]);
    }
  }
  #pragma unroll
  for (int i = 0; i < 8; i++) {
    float vv0 = acc[i][0], vv1 = acc[i][1], vv2 = acc[i][2], vv3 = acc[i][3];
    if (ACT) {
      vv0 = vv0 / (1.0f + __expf(-vv0));
      vv1 = vv1 / (1.0f + __expf(-vv1));
      vv2 = vv2 / (1.0f + __expf(-vv2));
      vv3 = vv3 / (1.0f + __expf(-vv3));
    }
    *reinterpret_cast<float4*>(Cm + (rg + 16 * i) * 68 + cg * 4) =
        make_float4(vv0, vv1, vv2, vv3);
  }
}

// float4-A GEMM, K multiple of 4, A in smem (stride 68), B in GLOBAL (LDG).
template <int K, bool ACT>
__device__ __forceinline__ void gemm128v(const float* __restrict__ A,
                                         const float* __restrict__ B, int Bs,
                                         float* __restrict__ Cm, int tid) {
  int rg = tid >> 4, cg = tid & 15;
  float acc[8][4];
  #pragma unroll
  for (int i = 0; i < 8; i++) { acc[i][0] = 0.f; acc[i][1] = 0.f; acc[i][2] = 0.f; acc[i][3] = 0.f; }
  #pragma unroll 2
  for (int k0 = 0; k0 < K; k0 += 4) {
    float4 b0 = *reinterpret_cast<const float4*>(B + (k0 + 0) * Bs + cg * 4);
    float4 b1 = *reinterpret_cast<const float4*>(B + (k0 + 1) * Bs + cg * 4);
    float4 b2 = *reinterpret_cast<const float4*>(B + (k0 + 2) * Bs + cg * 4);
    float4 b3 = *reinterpret_cast<const float4*>(B + (k0 + 3) * Bs + cg * 4);
    #pragma unroll
    for (int i = 0; i < 8; i++) {
      float4 a = *reinterpret_cast<const float4*>(A + (rg + 16 * i) * 68 + k0);
      acc[i][0] = fmaf(a.x, b0.x, acc[i][0]);
      acc[i][1] = fmaf(a.x, b0.y, acc[i][1]);
      acc[i][2] = fmaf(a.x, b0.z, acc[i][2]);
      acc[i][3] = fmaf(a.x, b0.w, acc[i][3]);
      acc[i][0] = fmaf(a.y, b1.x, acc[i][0]);
      acc[i][1] = fmaf(a.y, b1.y, acc[i][1]);
      acc[i][2] = fmaf(a.y, b1.z, acc[i][2]);
      acc[i][3] = fmaf(a.y, b1.w, acc[i][3]);
      acc[i][0] = fmaf(a.z, b2.x, acc[i][0]);
      acc[i][1] = fmaf(a.z, b2.y, acc[i][1]);
      acc[i][2] = fmaf(a.z, b2.z, acc[i][2]);
      acc[i][3] = fmaf(a.z, b2.w, acc[i][3]);
      acc[i][0] = fmaf(a.w, b3.x, acc[i][0]);
      acc[i][1] = fmaf(a.w, b3.y, acc[i][1]);
      acc[i][2] = fmaf(a.w, b3.z, acc[i][2]);
      acc[i][3] = fmaf(a.w, b3.w, acc[i][3]);
    }
  }
  #pragma unroll
  for (int i = 0; i < 8; i++) {
    float vv0 = acc[i][0], vv1 = acc[i][1], vv2 = acc[i][2], vv3 = acc[i][3];
    if (ACT) {
      vv0 = vv0 / (1.0f + __expf(-vv0));
      vv1 = vv1 / (1.0f + __expf(-vv1));
      vv2 = vv2 / (1.0f + __expf(-vv2));
      vv3 = vv3 / (1.0f + __expf(-vv3));
    }
    *reinterpret_cast<float4*>(Cm + (rg + 16 * i) * 68 + cg * 4) =
        make_float4(vv0, vv1, vv2, vv3);
  }
}

extern __shared__ float esmem_raw[];

// warp-per-edge scatter, lanes cover channels, plain atomicAdd. Y via LDG.
__device__ __forceinline__ void scatter_l(const ESmem3& s, int l, int tid, int eg0) {
  int wid = tid >> 5, lane = tid & 31;
  int lm0 = (l == 0) ? 0 : ((l == 1) ? 1 : 4);
  int cnt = (l == 0) ? 1 : ((l == 1) ? 3 : 5);
  for (int e = wid; e < 128; e += 8) {
    int rv = s.recv[e];
    if (rv < 0) continue;
    int zz = s.zs[e];
    const float* Ye = g_Yb + (eg0 + e) * NLMD + lm0;
    #pragma unroll
    for (int half = 0; half < 2; half++) {
      int c = lane + 32 * half;
      float val = s.htab[zz * 64 + c] * s.Fb[e * 68 + c];
      float* mp = g_msg + rv * 576 + c;
      for (int q = 0; q < cnt; q++)
        atomicAdd(mp + (lm0 + q) * 64, val * Ye[q]);
    }
  }
}

__global__ void __launch_bounds__(256, 3)
edge_kernel(const float* __restrict__ pos, const int* __restrict__ ai,
            const int* __restrict__ ei,
            const float* __restrict__ w1, const float* __restrict__ w2,
            const float* __restrict__ w3, const float* __restrict__ w4, int E) {
  ESmem3& s = *reinterpret_cast<ESmem3*>(esmem_raw);
  int tid = threadIdx.x;
  int eg0 = blockIdx.x * 128;

  // stage species table only (2.5 KB)
  {
    float4* d = (float4*)s.htab;
    const float4* g = (const float4*)g_htable;
    for (int i = tid; i < ZDIM * CDIM / 4; i += 256) d[i] = g[i];
  }

  // geometry -> EF (overlaid at start of Fb, stride 9), Y -> g_Yb, recv, zs
  if (tid < 128) {
    int eg = eg0 + tid;
    float* ef = s.Fb + tid * 9;  // EF overlay
    if (eg < E) {
      int sd = ei[eg];
      int rv = ei[E + eg];
      float px = pos[3 * rv + 0] - pos[3 * sd + 0];
      float py = pos[3 * rv + 1] - pos[3 * sd + 1];
      float pz = pos[3 * rv + 2] - pos[3 * sd + 2];
      float r2 = px * px + py * py + pz * pz + 1e-12f;
      float r = sqrtf(r2);
      float inv = 1.0f / r;
      float ux = px * inv, uy = py * inv, uz = pz * inv;
      const float c3 = 1.73205080756888f;
      const float c5 = 2.23606797749979f;
      const float c15 = 3.87298334620742f;
      float* Y = g_Yb + eg * NLMD;
      Y[0] = 1.0f;
      Y[1] = c3 * ux; Y[2] = c3 * uy; Y[3] = c3 * uz;
      Y[4] = c15 * ux * uy; Y[5] = c15 * uy * uz;
      Y[6] = 0.5f * c5 * (3.0f * uz * uz - 1.0f);
      Y[7] = c15 * ux * uz;
      Y[8] = 0.5f * c15 * (ux * ux - uy * uy);
      float u = fminf(r * 0.2f, 1.0f);
      float u2 = u * u, u4 = u2 * u2, u6 = u4 * u2, u7 = u6 * u, u8 = u4 * u4;
      float fc = 1.0f - 28.0f * u6 + 48.0f * u7 - 21.0f * u8;
      float pref = 0.632455532033676f * inv * fc;
      float w = 0.628318530717958648f * r;
      #pragma unroll
      for (int nb = 1; nb <= 8; nb++) ef[nb - 1] = pref * sinf(w * (float)nb);
      s.recv[tid] = rv;
      s.zs[tid] = ai[sd];
    } else {
      #pragma unroll
      for (int q = 0; q < 8; q++) ef[q] = 0.f;
      s.recv[tid] = -1;
      s.zs[tid] = 0;
    }
  }
  __syncthreads();   // EF/recv/zs in smem + g_Yb globally visible to block

  // L1: EF(@Fb overlay, stride 9) @ w1(global) -> Fa
  gemm128<8, true>(s.Fb, 9, w1, 64, s.Fa, tid);
  __syncthreads();

  // L2: Fa @ w2(global) -> Fb
  gemm128v<64, true>(s.Fa, w2, 64, s.Fb, tid);
  __syncthreads();

  // L3: Fb @ w3(global) -> Fa
  gemm128v<64, true>(s.Fb, w3, 64, s.Fa, tid);
  __syncthreads();

  // L4 in 3 column chunks from w4 (stride 192), each followed by scatter
  #pragma unroll
  for (int l = 0; l < 3; l++) {
    gemm128v<64, false>(s.Fa, w4 + l * 64, 192, s.Fb, tid);
    __syncthreads();           // Fb(l) ready
    scatter_l(s, l, tid, eg0);
    __syncthreads();           // scatter done before Fb overwritten
  }
}

// ---------------- per-(node,channel) tensor contraction (symmetrized) -----
__global__ void __launch_bounds__(256, 4)
contract_kernel(const int* __restrict__ ai, const float* __restrict__ U1,
                const float* __restrict__ Wc3, const float* __restrict__ Wc2,
                const float* __restrict__ Wc1, int N) {
  __shared__ float4 sU3s[9 * 45];  // [i][pair] x p
  __shared__ float4 sU2s[45];
  __shared__ float4 sU1[9];
  __shared__ float sW3[ZDIM * 4 * CDIM];
  __shared__ float sW2[ZDIM * 4 * CDIM];
  __shared__ float sW1[ZDIM * 4 * CDIM];
  int tid = threadIdx.x;
  for (int i = tid; i < 9 * 45; i += 256) sU3s[i] = ((const float4*)g_U3s)[i];
  if (tid < 45) sU2s[tid] = ((const float4*)g_U2s)[tid];
  if (tid >= 64 && tid < 73) sU1[tid - 64] = ((const float4*)U1)[tid - 64];
  for (int i = tid; i < ZDIM * 64; i += 256) {
    ((float4*)sW3)[i] = ((const float4*)Wc3)[i];
    ((float4*)sW2)[i] = ((const float4*)Wc2)[i];
    ((float4*)sW1)[i] = ((const float4*)Wc1)[i];
  }
  __syncthreads();

  int idx = blockIdx.x * 256 + tid;
  if (idx >= N * 64) return;
  int n = idx >> 6, c = idx & 63;
  int z = ai[n];

  float x[9];
  const float* mrow = g_msg + n * 576 + c;
  #pragma unroll
  for (int i = 0; i < 9; i++) x[i] = mrow[i * 64] * (1.0f / 16.0f);  // /AVG

  float w3p0 = sW3[z * 256 + 0 * 64 + c], w3p1 = sW3[z * 256 + 1 * 64 + c];
  float w3p2 = sW3[z * 256 + 2 * 64 + c], w3p3 = sW3[z * 256 + 3 * 64 + c];
  float w2p0 = sW2[z * 256 + 0 * 64 + c], w2p1 = sW2[z * 256 + 1 * 64 + c];
  float w2p2 = sW2[z * 256 + 2 * 64 + c], w2p3 = sW2[z * 256 + 3 * 64 + c];
  float w1p0 = sW1[z * 256 + 0 * 64 + c], w1p1 = sW1[z * 256 + 1 * 64 + c];
  float w1p2 = sW1[z * 256 + 2 * 64 + c], w1p3 = sW1[z * 256 + 3 * 64 + c];

  float res = 0.f;
  int pr = 0;
  for (int j = 0; j < 9; j++) {
    float xj = x[j];
    for (int k = j; k < 9; k++, pr++) {
      float X2 = xj * x[k];
      float s0 = 0.f, s1 = 0.f, s2 = 0.f, s3 = 0.f;
      #pragma unroll
      for (int i = 0; i < 9; i++) {
        float4 u3 = sU3s[i * 45 + pr];
        float xi = x[i];
        s0 = fmaf(u3.x, xi, s0);
        s1 = fmaf(u3.y, xi, s1);
        s2 = fmaf(u3.z, xi, s2);
        s3 = fmaf(u3.w, xi, s3);
      }
      float4 u2 = sU2s[pr];
      float t = u2.x * w2p0 + u2.y * w2p1 + u2.z * w2p2 + u2.w * w2p3;
      t = fmaf(s0, w3p0, t);
      t = fmaf(s1, w3p1, t);
      t = fmaf(s2, w3p2, t);
      t = fmaf(s3, w3p3, t);
      res = fmaf(t, X2, res);
    }
  }
  #pragma unroll
  for (int j = 0; j < 9; j++) {
    float4 u1 = sU1[j];
    float v = u1.x * w1p0 + u1.y * w1p1 + u1.z * w1p2 + u1.w * w1p3;
    res = fmaf(v, x[j], res);
  }
  g_xout[idx] = res;
}

// ---------------- final output GEMM: out = xout @ W_out / 8 ----------------
__global__ void __launch_bounds__(256)
out_kernel(const float* __restrict__ W_out, float* __restrict__ out, int N) {
  __shared__ float sW[64 * 64];
  __shared__ float sX[64 * 68];
  int tid = threadIdx.x;
  int n0 = blockIdx.x * 64;
  for (int i = tid; i < 1024; i += 256) ((float4*)sW)[i] = ((const float4*)W_out)[i];
  for (int i = tid; i < 64 * 16; i += 256) {
    int r = i >> 4, c4 = i & 15;
    float4 v = make_float4(0.f, 0.f, 0.f, 0.f);
    if (n0 + r < N) v = *reinterpret_cast<const float4*>(g_xout + (n0 + r) * 64 + c4 * 4);
    *reinterpret_cast<float4*>(sX + r * 68 + c4 * 4) = v;
  }
  __syncthreads();
  int rg = tid >> 4, cg = tid & 15;
  float acc[4][4];
  #pragma unroll
  for (int i = 0; i < 4; i++) { acc[i][0] = 0.f; acc[i][1] = 0.f; acc[i][2] = 0.f; acc[i][3] = 0.f; }
  #pragma unroll 4
  for (int k = 0; k < 64; k++) {
    float4 b = *reinterpret_cast<const float4*>(sW + k * 64 + cg * 4);
    #pragma unroll
    for (int i = 0; i < 4; i++) {
      float a = sX[(rg + 16 * i) * 68 + k];
      acc[i][0] = fmaf(a, b.x, acc[i][0]);
      acc[i][1] = fmaf(a, b.y, acc[i][1]);
      acc[i][2] = fmaf(a, b.z, acc[i][2]);
      acc[i][3] = fmaf(a, b.w, acc[i][3]);
    }
  }
  #pragma unroll
  for (int i = 0; i < 4; i++) {
    int n = n0 + rg + 16 * i;
    if (n < N) {
      *reinterpret_cast<float4*>(out + n * 64 + cg * 4) =
          make_float4(acc[i][0] * 0.125f, acc[i][1] * 0.125f,
                      acc[i][2] * 0.125f, acc[i][3] * 0.125f);
    }
  }
}

// ---------------- launch ----------------
extern "C" void kernel_launch(void* const* d_in, const int* in_sizes, int n_in,
                              void* d_out, int out_size) {
  const float* positions = (const float*)d_in[0];
  const int*   ai        = (const int*)d_in[1];
  const int*   ei        = (const int*)d_in[2];
  const float* W_embed   = (const float*)d_in[3];
  const float* W_up      = (const float*)d_in[4];
  const float* w1        = (const float*)d_in[5];
  const float* w2        = (const float*)d_in[6];
  const float* w3        = (const float*)d_in[7];
  const float* w4        = (const float*)d_in[8];
  const float* U3        = (const float*)d_in[9];
  const float* U2        = (const float*)d_in[10];
  const float* U1        = (const float*)d_in[11];
  const float* Wc3       = (const float*)d_in[12];
  const float* Wc2       = (const float*)d_in[13];
  const float* Wc1       = (const float*)d_in[14];
  const float* W_out     = (const float*)d_in[15];
  float* out = (float*)d_out;

  int N = in_sizes[0] / 3;
  int E = in_sizes[2] / 2;

  cudaFuncSetAttribute(edge_kernel, cudaFuncAttributeMaxDynamicSharedMemorySize,
                       (int)sizeof(ESmem3));

  int msg4 = (N * 576) / 4;
  zero_msg_kernel<<<(msg4 + 255) / 256, 256>>>(msg4);
  htable_kernel<<<1, 640>>>(W_embed, W_up);
  symU_kernel<<<2, 256>>>(U3, U2);
  int ntiles = (E + 127) / 128;
  edge_kernel<<<ntiles, 256, sizeof(ESmem3)>>>(positions, ai, ei, w1, w2, w3, w4, E);
  int nc = N * 64;
  contract_kernel<<<(nc + 255) / 256, 256>>>(ai, U1, Wc3, Wc2, Wc1, N);
  out_kernel<<<(N + 63) / 64, 256>>>(W_out, out, N);

  (void)n_in; (void)out_size;
}

// round 12
// speedup vs baseline: 1.1439x; 1.1439x over previous
#include <cuda_runtime.h>
#include <math.h>

#define NMAX 20000
#define CDIM 64
#define NLMD 9
#define NBES 8
#define ZDIM 10

// ---------------- helpers ----------------
__device__ __forceinline__ void red2(float* p, float a, float b) {
  asm volatile("red.global.add.v2.f32 [%0], {%1, %2};" :: "l"(p), "f"(a), "f"(b) : "memory");
}

// ---------------- scratch (device globals; no allocation) ----------------
__device__ float g_msg[NMAX * NLMD * CDIM];   // [N][lm][c]  46.08 MB
__device__ float g_htable[ZDIM * CDIM];
__device__ float g_xout[NMAX * CDIM];
__device__ float g_U3s[NLMD * 45 * 4];        // symmetrized U3: [i][pair][p]
__device__ float g_U2s[45 * 4];               // symmetrized U2: [pair][p]

// ---------------- zero the message buffer ----------------
__global__ void zero_msg_kernel(int n4) {
  int i = blockIdx.x * blockDim.x + threadIdx.x;
  float4* p = reinterpret_cast<float4*>(g_msg);
  if (i < n4) p[i] = make_float4(0.f, 0.f, 0.f, 0.f);
}

// ---------------- species embedding table ----------------
__global__ void htable_kernel(const float* __restrict__ W_embed,
                              const float* __restrict__ W_up) {
  int t = threadIdx.x;
  if (t < ZDIM * CDIM) {
    int z = t >> 6, c = t & 63;
    float acc = 0.f;
    #pragma unroll 8
    for (int k = 0; k < CDIM; k++)
      acc = fmaf(W_embed[z * CDIM + k], W_up[k * CDIM + c], acc);
    g_htable[t] = acc * (1.0f / (3.16227766016838f * 8.0f));  // /(sqrt(10)*sqrt(64))
  }
}

// ---------------- symmetrize U3/U2 over (j,k) ----------------
__global__ void symU_kernel(const float* __restrict__ U3,
                            const float* __restrict__ U2) {
  int t = blockIdx.x * blockDim.x + threadIdx.x;
  if (t >= 9 * 45) return;
  int i = t / 45, pr = t % 45;
  int j = 0, k = 0, acc = 0;
  for (int jj = 0; jj < 9; jj++) {
    int cnt = 9 - jj;
    if (pr < acc + cnt) { j = jj; k = jj + (pr - acc); break; }
    acc += cnt;
  }
  #pragma unroll
  for (int p = 0; p < 4; p++) {
    float v = U3[((i * 9 + j) * 9 + k) * 4 + p];
    if (j != k) v += U3[((i * 9 + k) * 9 + j) * 4 + p];
    g_U3s[(i * 45 + pr) * 4 + p] = v;
  }
  if (i == 0) {
    #pragma unroll
    for (int p = 0; p < 4; p++) {
      float v = U2[(j * 9 + k) * 4 + p];
      if (j != k) v += U2[(k * 9 + j) * 4 + p];
      g_U2s[pr * 4 + p] = v;
    }
  }
}

// ---------------- fused edge kernel (2 blocks/SM, chunked weights) --------
struct ESmem2 {
  float wbuf[2][4096];     // double-buffered 64x64 weight chunk
  float w1s[NBES * CDIM];
  float htab[ZDIM * CDIM];
  float Fa[128 * 68];      // activation ping
  float Fb[128 * 68];      // activation pong; EF (stride 9) overlaid at start
  float Yb[128 * 9];
  int   recv[128];
  int   zs[128];
};

// Scalar-A GEMM (used for layer 1 only; A stride not 16B-aligned).
template <int K, bool ACT>
__device__ __forceinline__ void gemm128(const float* __restrict__ A, int As,
                                        const float* __restrict__ B,
                                        float* __restrict__ Cm, int tid) {
  int rg = tid >> 4, cg = tid & 15;
  float acc[8][4];
  #pragma unroll
  for (int i = 0; i < 8; i++) { acc[i][0] = 0.f; acc[i][1] = 0.f; acc[i][2] = 0.f; acc[i][3] = 0.f; }
  #pragma unroll 4
  for (int k = 0; k < K; k++) {
    float4 b = *reinterpret_cast<const float4*>(B + k * 64 + cg * 4);
    #pragma unroll
    for (int i = 0; i < 8; i++) {
      float a = A[(rg + 16 * i) * As + k];
      acc[i][0] = fmaf(a, b.x, acc[i][0]);
      acc[i][1] = fmaf(a, b.y, acc[i][1]);
      acc[i][2] = fmaf(a, b.z, acc[i][2]);
      acc[i][3] = fmaf(a, b.w, acc[i][3]);
    }
  }
  #pragma unroll
  for (int i = 0; i < 8; i++) {
    float vv0 = acc[i][0], vv1 = acc[i][1], vv2 = acc[i][2], vv3 = acc[i][3];
    if (ACT) {
      vv0 = vv0 / (1.0f + __expf(-vv0));
      vv1 = vv1 / (1.0f + __expf(-vv1));
      vv2 = vv2 / (1.0f + __expf(-vv2));
      vv3 = vv3 / (1.0f + __expf(-vv3));
    }
    *reinterpret_cast<float4*>(Cm + (rg + 16 * i) * 68 + cg * 4) =
        make_float4(vv0, vv1, vv2, vv3);
  }
}

// float4-A GEMM, K multiple of 4, A stride 68 (16B-aligned rows), B in smem.
template <int K, bool ACT>
__device__ __forceinline__ void gemm128v(const float* __restrict__ A,
                                         const float* __restrict__ B,
                                         float* __restrict__ Cm, int tid) {
  int rg = tid >> 4, cg = tid & 15;
  float acc[8][4];
  #pragma unroll
  for (int i = 0; i < 8; i++) { acc[i][0] = 0.f; acc[i][1] = 0.f; acc[i][2] = 0.f; acc[i][3] = 0.f; }
  #pragma unroll 2
  for (int k0 = 0; k0 < K; k0 += 4) {
    float4 b0 = *reinterpret_cast<const float4*>(B + (k0 + 0) * 64 + cg * 4);
    float4 b1 = *reinterpret_cast<const float4*>(B + (k0 + 1) * 64 + cg * 4);
    float4 b2 = *reinterpret_cast<const float4*>(B + (k0 + 2) * 64 + cg * 4);
    float4 b3 = *reinterpret_cast<const float4*>(B + (k0 + 3) * 64 + cg * 4);
    #pragma unroll
    for (int i = 0; i < 8; i++) {
      float4 a = *reinterpret_cast<const float4*>(A + (rg + 16 * i) * 68 + k0);
      acc[i][0] = fmaf(a.x, b0.x, acc[i][0]);
      acc[i][1] = fmaf(a.x, b0.y, acc[i][1]);
      acc[i][2] = fmaf(a.x, b0.z, acc[i][2]);
      acc[i][3] = fmaf(a.x, b0.w, acc[i][3]);
      acc[i][0] = fmaf(a.y, b1.x, acc[i][0]);
      acc[i][1] = fmaf(a.y, b1.y, acc[i][1]);
      acc[i][2] = fmaf(a.y, b1.z, acc[i][2]);
      acc[i][3] = fmaf(a.y, b1.w, acc[i][3]);
      acc[i][0] = fmaf(a.z, b2.x, acc[i][0]);
      acc[i][1] = fmaf(a.z, b2.y, acc[i][1]);
      acc[i][2] = fmaf(a.z, b2.z, acc[i][2]);
      acc[i][3] = fmaf(a.z, b2.w, acc[i][3]);
      acc[i][0] = fmaf(a.w, b3.x, acc[i][0]);
      acc[i][1] = fmaf(a.w, b3.y, acc[i][1]);
      acc[i][2] = fmaf(a.w, b3.z, acc[i][2]);
      acc[i][3] = fmaf(a.w, b3.w, acc[i][3]);
    }
  }
  #pragma unroll
  for (int i = 0; i < 8; i++) {
    float vv0 = acc[i][0], vv1 = acc[i][1], vv2 = acc[i][2], vv3 = acc[i][3];
    if (ACT) {
      vv0 = vv0 / (1.0f + __expf(-vv0));
      vv1 = vv1 / (1.0f + __expf(-vv1));
      vv2 = vv2 / (1.0f + __expf(-vv2));
      vv3 = vv3 / (1.0f + __expf(-vv3));
    }
    *reinterpret_cast<float4*>(Cm + (rg + 16 * i) * 68 + cg * 4) =
        make_float4(vv0, vv1, vv2, vv3);
  }
}

// load one 64x64 chunk of w4 (cols l*64..) into registers
__device__ __forceinline__ void load_w4chunk(float4 pre[4], const float* __restrict__ w4,
                                             int l, int tid) {
  #pragma unroll
  for (int q = 0; q < 4; q++) {
    int f = tid + q * 256, k = f >> 4, c4 = f & 15;
    pre[q] = *reinterpret_cast<const float4*>(w4 + k * 192 + l * 64 + c4 * 4);
  }
}
__device__ __forceinline__ void store_chunk(float* __restrict__ sm, float4 pre[4], int tid) {
  #pragma unroll
  for (int q = 0; q < 4; q++)
    reinterpret_cast<float4*>(sm)[tid + q * 256] = pre[q];
}

extern __shared__ float esmem_raw[];

// warp-per-edge scatter, lanes cover channel PAIRS, red.global.add.v2.f32
__device__ __forceinline__ void scatter_l(const ESmem2& s, int l, int tid) {
  int wid = tid >> 5, lane = tid & 31;
  int lm0 = (l == 0) ? 0 : ((l == 1) ? 1 : 4);
  int cnt = (l == 0) ? 1 : ((l == 1) ? 3 : 5);
  int c0 = 2 * lane;
  for (int e = wid; e < 128; e += 8) {
    int rv = s.recv[e];
    if (rv < 0) continue;
    int zz = s.zs[e];
    float2 h2 = *reinterpret_cast<const float2*>(s.htab + zz * 64 + c0);
    float2 f2 = *reinterpret_cast<const float2*>(s.Fb + e * 68 + c0);
    float v0 = h2.x * f2.x;
    float v1 = h2.y * f2.y;
    float* mp = g_msg + rv * 576 + c0;
    const float* Ye = s.Yb + e * 9 + lm0;
    for (int q = 0; q < cnt; q++) {
      float yv = Ye[q];
      red2(mp + (lm0 + q) * 64, v0 * yv, v1 * yv);
    }
  }
}

__global__ void __launch_bounds__(256, 2)
edge_kernel(const float* __restrict__ pos, const int* __restrict__ ai,
            const int* __restrict__ ei,
            const float* __restrict__ w1, const float* __restrict__ w2,
            const float* __restrict__ w3, const float* __restrict__ w4, int E) {
  ESmem2& s = *reinterpret_cast<ESmem2*>(esmem_raw);
  int tid = threadIdx.x;

  // phase 0: stage w1, htab, w2->wbuf0, w3->wbuf1
  {
    float4* d; const float4* g;
    d = (float4*)s.w1s;  g = (const float4*)w1;       for (int i = tid; i < NBES * CDIM / 4; i += 256) d[i] = g[i];
    d = (float4*)s.htab; g = (const float4*)g_htable; for (int i = tid; i < ZDIM * CDIM / 4; i += 256) d[i] = g[i];
    d = (float4*)s.wbuf[0]; g = (const float4*)w2;    for (int i = tid; i < 1024; i += 256) d[i] = g[i];
    d = (float4*)s.wbuf[1]; g = (const float4*)w3;    for (int i = tid; i < 1024; i += 256) d[i] = g[i];
  }

  // geometry -> EF (overlaid at start of Fb, stride 9), Yb, recv, zs
  if (tid < 128) {
    int eg = blockIdx.x * 128 + tid;
    float* Y  = s.Yb + tid * 9;
    float* ef = s.Fb + tid * 9;  // EF overlay
    if (eg < E) {
      int sd = ei[eg];
      int rv = ei[E + eg];
      float px = pos[3 * rv + 0] - pos[3 * sd + 0];
      float py = pos[3 * rv + 1] - pos[3 * sd + 1];
      float pz = pos[3 * rv + 2] - pos[3 * sd + 2];
      float r2 = px * px + py * py + pz * pz + 1e-12f;
      float r = sqrtf(r2);
      float inv = 1.0f / r;
      float ux = px * inv, uy = py * inv, uz = pz * inv;
      const float c3 = 1.73205080756888f;
      const float c5 = 2.23606797749979f;
      const float c15 = 3.87298334620742f;
      Y[0] = 1.0f;
      Y[1] = c3 * ux; Y[2] = c3 * uy; Y[3] = c3 * uz;
      Y[4] = c15 * ux * uy; Y[5] = c15 * uy * uz;
      Y[6] = 0.5f * c5 * (3.0f * uz * uz - 1.0f);
      Y[7] = c15 * ux * uz;
      Y[8] = 0.5f * c15 * (ux * ux - uy * uy);
      float u = fminf(r * 0.2f, 1.0f);
      float u2 = u * u, u4 = u2 * u2, u6 = u4 * u2, u7 = u6 * u, u8 = u4 * u4;
      float fc = 1.0f - 28.0f * u6 + 48.0f * u7 - 21.0f * u8;
      float pref = 0.632455532033676f * inv * fc;
      float w = 0.628318530717958648f * r;
      #pragma unroll
      for (int nb = 1; nb <= 8; nb++) ef[nb - 1] = pref * sinf(w * (float)nb);
      s.recv[tid] = rv;
      s.zs[tid] = ai[sd];
    } else {
      #pragma unroll
      for (int q = 0; q < 9; q++) Y[q] = 0.f;
      #pragma unroll
      for (int q = 0; q < 8; q++) ef[q] = 0.f;
      s.recv[tid] = -1;
      s.zs[tid] = 0;
    }
  }
  __syncthreads();

  // L1: EF(@Fb overlay, stride 9) @ w1 -> Fa  (scalar-A path)
  gemm128<8, true>(s.Fb, 9, s.w1s, s.Fa, tid);
  __syncthreads();

  // L2: Fa @ w2(wbuf0) -> Fb   (prefetch w4 chunk 0 during)
  float4 preA[4], preB[4];
  load_w4chunk(preA, w4, 0, tid);
  gemm128v<64, true>(s.Fa, s.wbuf[0], s.Fb, tid);
  __syncthreads();                       // Fb ready, wbuf0 free

  store_chunk(s.wbuf[0], preA, tid);     // wbuf0 <- w4 chunk 0
  load_w4chunk(preB, w4, 1, tid);
  // L3: Fb @ w3(wbuf1) -> Fa
  gemm128v<64, true>(s.Fb, s.wbuf[1], s.Fa, tid);
  __syncthreads();                       // Fa ready, wbuf1 free, wbuf0 visible

  store_chunk(s.wbuf[1], preB, tid);     // wbuf1 <- w4 chunk 1
  load_w4chunk(preA, w4, 2, tid);
  // L4 chunk 0: Fa @ w4a(wbuf0) -> Fb, scatter l=0
  gemm128v<64, false>(s.Fa, s.wbuf[0], s.Fb, tid);
  __syncthreads();                       // Fb(l0) ready, wbuf1 visible
  scatter_l(s, 0, tid);
  __syncthreads();                       // scatter done before Fb overwritten; wbuf0 free

  store_chunk(s.wbuf[0], preA, tid);     // wbuf0 <- w4 chunk 2
  // L4 chunk 1
  gemm128v<64, false>(s.Fa, s.wbuf[1], s.Fb, tid);
  __syncthreads();                       // Fb(l1) ready, wbuf0 visible
  scatter_l(s, 1, tid);
  __syncthreads();
  // L4 chunk 2
  gemm128v<64, false>(s.Fa, s.wbuf[0], s.Fb, tid);
  __syncthreads();
  scatter_l(s, 2, tid);
}

// ---------------- per-(node, 2-channel) tensor contraction (symmetrized) --
// Each thread computes 2 channels; every U3s/U2s broadcast LDS serves both.
__global__ void __launch_bounds__(256, 3)
contract_kernel(const int* __restrict__ ai, const float* __restrict__ U1,
                const float* __restrict__ Wc3, const float* __restrict__ Wc2,
                const float* __restrict__ Wc1, int N) {
  __shared__ float4 sU3s[9 * 45];  // [i][pair] x p
  __shared__ float4 sU2s[45];
  __shared__ float4 sU1[9];
  __shared__ float sW3[ZDIM * 4 * CDIM];
  __shared__ float sW2[ZDIM * 4 * CDIM];
  __shared__ float sW1[ZDIM * 4 * CDIM];
  int tid = threadIdx.x;
  for (int i = tid; i < 9 * 45; i += 256) sU3s[i] = ((const float4*)g_U3s)[i];
  if (tid < 45) sU2s[tid] = ((const float4*)g_U2s)[tid];
  if (tid >= 64 && tid < 73) sU1[tid - 64] = ((const float4*)U1)[tid - 64];
  for (int i = tid; i < ZDIM * 64; i += 256) {
    ((float4*)sW3)[i] = ((const float4*)Wc3)[i];
    ((float4*)sW2)[i] = ((const float4*)Wc2)[i];
    ((float4*)sW1)[i] = ((const float4*)Wc1)[i];
  }
  __syncthreads();

  int idx = blockIdx.x * 256 + tid;
  if (idx >= N * 32) return;
  int n = idx >> 5, q = idx & 31, c0 = 2 * q;
  int z = ai[n];

  float xa[9], xb[9];
  const float* mrow = g_msg + n * 576 + c0;
  #pragma unroll
  for (int i = 0; i < 9; i++) {
    float2 v = *reinterpret_cast<const float2*>(mrow + i * 64);
    xa[i] = v.x * (1.0f / 16.0f);
    xb[i] = v.y * (1.0f / 16.0f);
  }

  float2 w3p[4], w2p[4], w1p[4];
  #pragma unroll
  for (int p = 0; p < 4; p++) {
    w3p[p] = *reinterpret_cast<const float2*>(sW3 + z * 256 + p * 64 + c0);
    w2p[p] = *reinterpret_cast<const float2*>(sW2 + z * 256 + p * 64 + c0);
    w1p[p] = *reinterpret_cast<const float2*>(sW1 + z * 256 + p * 64 + c0);
  }

  float resA = 0.f, resB = 0.f;
  int pr = 0;
  for (int j = 0; j < 9; j++) {
    float xja = xa[j], xjb = xb[j];
    for (int k = j; k < 9; k++, pr++) {
      float X2a = xja * xa[k];
      float X2b = xjb * xb[k];
      float a0 = 0.f, a1 = 0.f, a2 = 0.f, a3 = 0.f;
      float b0 = 0.f, b1 = 0.f, b2 = 0.f, b3 = 0.f;
      #pragma unroll
      for (int i = 0; i < 9; i++) {
        float4 u3 = sU3s[i * 45 + pr];
        float xia = xa[i], xib = xb[i];
        a0 = fmaf(u3.x, xia, a0); b0 = fmaf(u3.x, xib, b0);
        a1 = fmaf(u3.y, xia, a1); b1 = fmaf(u3.y, xib, b1);
        a2 = fmaf(u3.z, xia, a2); b2 = fmaf(u3.z, xib, b2);
        a3 = fmaf(u3.w, xia, a3); b3 = fmaf(u3.w, xib, b3);
      }
      float4 u2 = sU2s[pr];
      float ta = u2.x * w2p[0].x + u2.y * w2p[1].x + u2.z * w2p[2].x + u2.w * w2p[3].x;
      float tb = u2.x * w2p[0].y + u2.y * w2p[1].y + u2.z * w2p[2].y + u2.w * w2p[3].y;
      ta = fmaf(a0, w3p[0].x, ta); tb = fmaf(b0, w3p[0].y, tb);
      ta = fmaf(a1, w3p[1].x, ta); tb = fmaf(b1, w3p[1].y, tb);
      ta = fmaf(a2, w3p[2].x, ta); tb = fmaf(b2, w3p[2].y, tb);
      ta = fmaf(a3, w3p[3].x, ta); tb = fmaf(b3, w3p[3].y, tb);
      resA = fmaf(ta, X2a, resA);
      resB = fmaf(tb, X2b, resB);
    }
  }
  #pragma unroll
  for (int j = 0; j < 9; j++) {
    float4 u1 = sU1[j];
    float va = u1.x * w1p[0].x + u1.y * w1p[1].x + u1.z * w1p[2].x + u1.w * w1p[3].x;
    float vb = u1.x * w1p[0].y + u1.y * w1p[1].y + u1.z * w1p[2].y + u1.w * w1p[3].y;
    resA = fmaf(va, xa[j], resA);
    resB = fmaf(vb, xb[j], resB);
  }
  *reinterpret_cast<float2*>(g_xout + n * 64 + c0) = make_float2(resA, resB);
}

// ---------------- final output GEMM: out = xout @ W_out / 8 ----------------
__global__ void __launch_bounds__(256)
out_kernel(const float* __restrict__ W_out, float* __restrict__ out, int N) {
  __shared__ float sW[64 * 64];
  __shared__ float sX[64 * 68];
  int tid = threadIdx.x;
  int n0 = blockIdx.x * 64;
  for (int i = tid; i < 1024; i += 256) ((float4*)sW)[i] = ((const float4*)W_out)[i];
  for (int i = tid; i < 64 * 16; i += 256) {
    int r = i >> 4, c4 = i & 15;
    float4 v = make_float4(0.f, 0.f, 0.f, 0.f);
    if (n0 + r < N) v = *reinterpret_cast<const float4*>(g_xout + (n0 + r) * 64 + c4 * 4);
    *reinterpret_cast<float4*>(sX + r * 68 + c4 * 4) = v;
  }
  __syncthreads();
  int rg = tid >> 4, cg = tid & 15;
  float acc[4][4];
  #pragma unroll
  for (int i = 0; i < 4; i++) { acc[i][0] = 0.f; acc[i][1] = 0.f; acc[i][2] = 0.f; acc[i][3] = 0.f; }
  #pragma unroll 4
  for (int k = 0; k < 64; k++) {
    float4 b = *reinterpret_cast<const float4*>(sW + k * 64 + cg * 4);
    #pragma unroll
    for (int i = 0; i < 4; i++) {
      float a = sX[(rg + 16 * i) * 68 + k];
      acc[i][0] = fmaf(a, b.x, acc[i][0]);
      acc[i][1] = fmaf(a, b.y, acc[i][1]);
      acc[i][2] = fmaf(a, b.z, acc[i][2]);
      acc[i][3] = fmaf(a, b.w, acc[i][3]);
    }
  }
  #pragma unroll
  for (int i = 0; i < 4; i++) {
    int n = n0 + rg + 16 * i;
    if (n < N) {
      *reinterpret_cast<float4*>(out + n * 64 + cg * 4) =
          make_float4(acc[i][0] * 0.125f, acc[i][1] * 0.125f,
                      acc[i][2] * 0.125f, acc[i][3] * 0.125f);
    }
  }
}

// ---------------- launch ----------------
extern "C" void kernel_launch(void* const* d_in, const int* in_sizes, int n_in,
                              void* d_out, int out_size) {
  const float* positions = (const float*)d_in[0];
  const int*   ai        = (const int*)d_in[1];
  const int*   ei        = (const int*)d_in[2];
  const float* W_embed   = (const float*)d_in[3];
  const float* W_up      = (const float*)d_in[4];
  const float* w1        = (const float*)d_in[5];
  const float* w2        = (const float*)d_in[6];
  const float* w3        = (const float*)d_in[7];
  const float* w4        = (const float*)d_in[8];
  const float* U3        = (const float*)d_in[9];
  const float* U2        = (const float*)d_in[10];
  const float* U1        = (const float*)d_in[11];
  const float* Wc3       = (const float*)d_in[12];
  const float* Wc2       = (const float*)d_in[13];
  const float* Wc1       = (const float*)d_in[14];
  const float* W_out     = (const float*)d_in[15];
  float* out = (float*)d_out;

  int N = in_sizes[0] / 3;
  int E = in_sizes[2] / 2;

  cudaFuncSetAttribute(edge_kernel, cudaFuncAttributeMaxDynamicSharedMemorySize,
                       (int)sizeof(ESmem2));

  int msg4 = (N * 576) / 4;
  zero_msg_kernel<<<(msg4 + 255) / 256, 256>>>(msg4);
  htable_kernel<<<1, 640>>>(W_embed, W_up);
  symU_kernel<<<2, 256>>>(U3, U2);
  int ntiles = (E + 127) / 128;
  edge_kernel<<<ntiles, 256, sizeof(ESmem2)>>>(positions, ai, ei, w1, w2, w3, w4, E);
  int nc = N * 32;
  contract_kernel<<<(nc + 255) / 256, 256>>>(ai, U1, Wc3, Wc2, Wc1, N);
  out_kernel<<<(N + 63) / 64, 256>>>(W_out, out, N);

  (void)n_in; (void)out_size;
}

// round 14
// speedup vs baseline: 1.2210x; 1.0673x over previous
#include <cuda_runtime.h>
#include <math.h>

#define NMAX 20000
#define CDIM 64
#define NLMD 9
#define NBES 8
#define ZDIM 10

// ---------------- helpers ----------------
__device__ __forceinline__ void red2(float* p, float a, float b) {
  asm volatile("red.global.add.v2.f32 [%0], {%1, %2};" :: "l"(p), "f"(a), "f"(b) : "memory");
}

// ---------------- scratch (device globals; no allocation) ----------------
__device__ float g_msg[NMAX * NLMD * CDIM];   // [N][lm][c]  46.08 MB
__device__ float g_htable[ZDIM * CDIM];
__device__ float g_xout[NMAX * CDIM];
__device__ float g_U3s[NLMD * 45 * 4];        // symmetrized U3: [i][pair][p]
__device__ float g_U2s[45 * 4];               // symmetrized U2: [pair][p]

// ---------------- zero the message buffer ----------------
__global__ void zero_msg_kernel(int n4) {
  int i = blockIdx.x * blockDim.x + threadIdx.x;
  float4* p = reinterpret_cast<float4*>(g_msg);
  if (i < n4) p[i] = make_float4(0.f, 0.f, 0.f, 0.f);
}

// ---------------- species embedding table ----------------
__global__ void htable_kernel(const float* __restrict__ W_embed,
                              const float* __restrict__ W_up) {
  int t = threadIdx.x;
  if (t < ZDIM * CDIM) {
    int z = t >> 6, c = t & 63;
    float acc = 0.f;
    #pragma unroll 8
    for (int k = 0; k < CDIM; k++)
      acc = fmaf(W_embed[z * CDIM + k], W_up[k * CDIM + c], acc);
    g_htable[t] = acc * (1.0f / (3.16227766016838f * 8.0f));  // /(sqrt(10)*sqrt(64))
  }
}

// ---------------- symmetrize U3/U2 over (j,k) ----------------
__global__ void symU_kernel(const float* __restrict__ U3,
                            const float* __restrict__ U2) {
  int t = blockIdx.x * blockDim.x + threadIdx.x;
  if (t >= 9 * 45) return;
  int i = t / 45, pr = t % 45;
  int j = 0, k = 0, acc = 0;
  for (int jj = 0; jj < 9; jj++) {
    int cnt = 9 - jj;
    if (pr < acc + cnt) { j = jj; k = jj + (pr - acc); break; }
    acc += cnt;
  }
  #pragma unroll
  for (int p = 0; p < 4; p++) {
    float v = U3[((i * 9 + j) * 9 + k) * 4 + p];
    if (j != k) v += U3[((i * 9 + k) * 9 + j) * 4 + p];
    g_U3s[(i * 45 + pr) * 4 + p] = v;
  }
  if (i == 0) {
    #pragma unroll
    for (int p = 0; p < 4; p++) {
      float v = U2[(j * 9 + k) * 4 + p];
      if (j != k) v += U2[(k * 9 + j) * 4 + p];
      g_U2s[pr * 4 + p] = v;
    }
  }
}

// ---------------- fused edge kernel (3 blocks/SM, in-place GEMMs) ---------
struct ESmem3 {
  float ACT[128 * 68];     // activation buffer, in-place      (34816 B)
  float WB0[4096];         // weight buffer w2->w3->w4 chunks  (16384 B)
  float OUT[64 * 64];      // 64-row L4 output                 (16384 B)
  float htab[ZDIM * CDIM]; //                                  (2560 B)
  float einfo[128 * 8];    // {rv, zz, ux, uy, uz, -,-,-}      (4096 B)
};                         // total 74240 B -> 3 blocks/SM

// float4-A GEMM over 128 rows, K mult of 4; A stride 68, B stride 64.
// INPLACE: barrier between read-all-A and store (C aliases A).
template <int K, bool ACTF>
__device__ __forceinline__ void gemm128ip(const float* __restrict__ A,
                                          const float* __restrict__ B,
                                          float* __restrict__ Cm, int tid) {
  int rg = tid >> 4, cg = tid & 15;
  float acc[8][4];
  #pragma unroll
  for (int i = 0; i < 8; i++) { acc[i][0] = 0.f; acc[i][1] = 0.f; acc[i][2] = 0.f; acc[i][3] = 0.f; }
  #pragma unroll 1
  for (int k0 = 0; k0 < K; k0 += 4) {
    float4 b0 = *reinterpret_cast<const float4*>(B + (k0 + 0) * 64 + cg * 4);
    float4 b1 = *reinterpret_cast<const float4*>(B + (k0 + 1) * 64 + cg * 4);
    float4 b2 = *reinterpret_cast<const float4*>(B + (k0 + 2) * 64 + cg * 4);
    float4 b3 = *reinterpret_cast<const float4*>(B + (k0 + 3) * 64 + cg * 4);
    #pragma unroll
    for (int i = 0; i < 8; i++) {
      float4 a = *reinterpret_cast<const float4*>(A + (rg + 16 * i) * 68 + k0);
      acc[i][0] = fmaf(a.x, b0.x, acc[i][0]);
      acc[i][1] = fmaf(a.x, b0.y, acc[i][1]);
      acc[i][2] = fmaf(a.x, b0.z, acc[i][2]);
      acc[i][3] = fmaf(a.x, b0.w, acc[i][3]);
      acc[i][0] = fmaf(a.y, b1.x, acc[i][0]);
      acc[i][1] = fmaf(a.y, b1.y, acc[i][1]);
      acc[i][2] = fmaf(a.y, b1.z, acc[i][2]);
      acc[i][3] = fmaf(a.y, b1.w, acc[i][3]);
      acc[i][0] = fmaf(a.z, b2.x, acc[i][0]);
      acc[i][1] = fmaf(a.z, b2.y, acc[i][1]);
      acc[i][2] = fmaf(a.z, b2.z, acc[i][2]);
      acc[i][3] = fmaf(a.z, b2.w, acc[i][3]);
      acc[i][0] = fmaf(a.w, b3.x, acc[i][0]);
      acc[i][1] = fmaf(a.w, b3.y, acc[i][1]);
      acc[i][2] = fmaf(a.w, b3.z, acc[i][2]);
      acc[i][3] = fmaf(a.w, b3.w, acc[i][3]);
    }
  }
  __syncthreads();   // all reads of A complete before overwrite
  #pragma unroll
  for (int i = 0; i < 8; i++) {
    float vv0 = acc[i][0], vv1 = acc[i][1], vv2 = acc[i][2], vv3 = acc[i][3];
    if (ACTF) {
      vv0 = vv0 / (1.0f + __expf(-vv0));
      vv1 = vv1 / (1.0f + __expf(-vv1));
      vv2 = vv2 / (1.0f + __expf(-vv2));
      vv3 = vv3 / (1.0f + __expf(-vv3));
    }
    *reinterpret_cast<float4*>(Cm + (rg + 16 * i) * 68 + cg * 4) =
        make_float4(vv0, vv1, vv2, vv3);
  }
}

// 64-row GEMM: OUT[64x64] = A64[64xK=64 (stride 68)] @ B[64x64 (stride 64)]
__device__ __forceinline__ void gemm64(const float* __restrict__ A64,
                                       const float* __restrict__ B,
                                       float* __restrict__ Cm, int tid) {
  int rg = tid >> 4, cg = tid & 15;
  float acc[4][4];
  #pragma unroll
  for (int i = 0; i < 4; i++) { acc[i][0] = 0.f; acc[i][1] = 0.f; acc[i][2] = 0.f; acc[i][3] = 0.f; }
  #pragma unroll 2
  for (int k0 = 0; k0 < 64; k0 += 4) {
    float4 b0 = *reinterpret_cast<const float4*>(B + (k0 + 0) * 64 + cg * 4);
    float4 b1 = *reinterpret_cast<const float4*>(B + (k0 + 1) * 64 + cg * 4);
    float4 b2 = *reinterpret_cast<const float4*>(B + (k0 + 2) * 64 + cg * 4);
    float4 b3 = *reinterpret_cast<const float4*>(B + (k0 + 3) * 64 + cg * 4);
    #pragma unroll
    for (int i = 0; i < 4; i++) {
      float4 a = *reinterpret_cast<const float4*>(A64 + (rg + 16 * i) * 68 + k0);
      acc[i][0] = fmaf(a.x, b0.x, acc[i][0]);
      acc[i][1] = fmaf(a.x, b0.y, acc[i][1]);
      acc[i][2] = fmaf(a.x, b0.z, acc[i][2]);
      acc[i][3] = fmaf(a.x, b0.w, acc[i][3]);
      acc[i][0] = fmaf(a.y, b1.x, acc[i][0]);
      acc[i][1] = fmaf(a.y, b1.y, acc[i][1]);
      acc[i][2] = fmaf(a.y, b1.z, acc[i][2]);
      acc[i][3] = fmaf(a.y, b1.w, acc[i][3]);
      acc[i][0] = fmaf(a.z, b2.x, acc[i][0]);
      acc[i][1] = fmaf(a.z, b2.y, acc[i][1]);
      acc[i][2] = fmaf(a.z, b2.z, acc[i][2]);
      acc[i][3] = fmaf(a.z, b2.w, acc[i][3]);
      acc[i][0] = fmaf(a.w, b3.x, acc[i][0]);
      acc[i][1] = fmaf(a.w, b3.y, acc[i][1]);
      acc[i][2] = fmaf(a.w, b3.z, acc[i][2]);
      acc[i][3] = fmaf(a.w, b3.w, acc[i][3]);
    }
  }
  #pragma unroll
  for (int i = 0; i < 4; i++) {
    *reinterpret_cast<float4*>(Cm + (rg + 16 * i) * 64 + cg * 4) =
        make_float4(acc[i][0], acc[i][1], acc[i][2], acc[i][3]);
  }
}

// copy a 64x64 block (row stride src_stride, col offset c0) into dst (stride 64)
__device__ __forceinline__ void copy_w(float* __restrict__ dst,
                                       const float* __restrict__ src,
                                       int src_stride, int c0, int tid) {
  #pragma unroll
  for (int q = 0; q < 4; q++) {
    int f = tid + q * 256, k = f >> 4, c4 = f & 15;
    *reinterpret_cast<float4*>(dst + k * 64 + c4 * 4) =
        *reinterpret_cast<const float4*>(src + k * src_stride + c0 + c4 * 4);
  }
}

extern __shared__ float esmem_raw[];

// scatter one 64-edge half: warp-per-edge, lanes = channel pairs, Y recomputed
__device__ __forceinline__ void scatter_h(const float* __restrict__ OUTb,
                                          const float* __restrict__ htab,
                                          const float* __restrict__ einfo,
                                          int l, int h, int tid) {
  int wid = tid >> 5, lane = tid & 31;
  int lm0 = (l == 0) ? 0 : ((l == 1) ? 1 : 4);
  int cnt = (l == 0) ? 1 : ((l == 1) ? 3 : 5);
  int c0 = 2 * lane;
  const float c3 = 1.73205080756888f;
  const float c5 = 2.23606797749979f;
  const float c15 = 3.87298334620742f;
  #pragma unroll
  for (int i = 0; i < 8; i++) {
    int el = wid + 8 * i;            // local row in OUT (0..63)
    int e = h * 64 + el;             // edge index in tile
    const float* ei = einfo + e * 8;
    int rv = __float_as_int(ei[0]);
    if (rv < 0) continue;
    int zz = __float_as_int(ei[1]);
    float ux = ei[2], uy = ei[3], uz = ei[4];
    float Y[5];
    if (l == 0) {
      Y[0] = 1.0f;
    } else if (l == 1) {
      Y[0] = c3 * ux; Y[1] = c3 * uy; Y[2] = c3 * uz;
    } else {
      Y[0] = c15 * ux * uy;
      Y[1] = c15 * uy * uz;
      Y[2] = 0.5f * c5 * (3.0f * uz * uz - 1.0f);
      Y[3] = c15 * ux * uz;
      Y[4] = 0.5f * c15 * (ux * ux - uy * uy);
    }
    float2 h2 = *reinterpret_cast<const float2*>(htab + zz * 64 + c0);
    float2 f2 = *reinterpret_cast<const float2*>(OUTb + el * 64 + c0);
    float v0 = h2.x * f2.x;
    float v1 = h2.y * f2.y;
    float* mp = g_msg + rv * 576 + c0;
    #pragma unroll
    for (int q = 0; q < 5; q++) {
      if (q < cnt) red2(mp + (lm0 + q) * 64, v0 * Y[q], v1 * Y[q]);
    }
  }
}

__global__ void __launch_bounds__(256, 3)
edge_kernel(const float* __restrict__ pos, const int* __restrict__ ai,
            const int* __restrict__ ei,
            const float* __restrict__ w1, const float* __restrict__ w2,
            const float* __restrict__ w3, const float* __restrict__ w4, int E) {
  ESmem3& s = *reinterpret_cast<ESmem3*>(esmem_raw);
  int tid = threadIdx.x;

  // phase 0: stage htab, WB0<-w2
  {
    float4* d; const float4* g;
    d = (float4*)s.htab; g = (const float4*)g_htable; for (int i = tid; i < ZDIM * CDIM / 4; i += 256) d[i] = g[i];
  }
  copy_w(s.WB0, w2, 64, 0, tid);

  // geometry: EF into ACT (stride 68, cols 0..7), einfo {rv, zz, u}
  if (tid < 128) {
    int eg = blockIdx.x * 128 + tid;
    float* ef = s.ACT + tid * 68;
    float* einf = s.einfo + tid * 8;
    if (eg < E) {
      int sd = ei[eg];
      int rv = ei[E + eg];
      float px = pos[3 * rv + 0] - pos[3 * sd + 0];
      float py = pos[3 * rv + 1] - pos[3 * sd + 1];
      float pz = pos[3 * rv + 2] - pos[3 * sd + 2];
      float r2 = px * px + py * py + pz * pz + 1e-12f;
      float r = sqrtf(r2);
      float inv = 1.0f / r;
      float ux = px * inv, uy = py * inv, uz = pz * inv;
      float u = fminf(r * 0.2f, 1.0f);
      float u2 = u * u, u4 = u2 * u2, u6 = u4 * u2, u7 = u6 * u, u8 = u4 * u4;
      float fc = 1.0f - 28.0f * u6 + 48.0f * u7 - 21.0f * u8;
      float pref = 0.632455532033676f * inv * fc;   // sqrt(2/RMAX)/r * fcut
      float w = 0.628318530717958648f * r;          // pi*r/RMAX
      #pragma unroll
      for (int nb = 1; nb <= 8; nb++) ef[nb - 1] = pref * sinf(w * (float)nb);
      einf[0] = __int_as_float(rv);
      einf[1] = __int_as_float(ai[sd]);
      einf[2] = ux; einf[3] = uy; einf[4] = uz;
    } else {
      #pragma unroll
      for (int q = 0; q < 8; q++) ef[q] = 0.f;
      einf[0] = __int_as_float(-1);
      einf[1] = 0.f; einf[2] = 0.f; einf[3] = 0.f; einf[4] = 0.f;
    }
  }
  __syncthreads();

  // L1: ACT(cols 0..7) @ w1 (global LDG, 8x64, L1-resident) -> ACT in-place
  gemm128ip<8, true>(s.ACT, w1, s.ACT, tid);
  __syncthreads();

  // L2: ACT @ w2(WB0) -> ACT in-place
  gemm128ip<64, true>(s.ACT, s.WB0, s.ACT, tid);
  __syncthreads();                      // WB0 reads done, ACT(L2) visible

  copy_w(s.WB0, w3, 64, 0, tid);        // WB0 <- w3
  __syncthreads();

  // L3: ACT @ w3(WB0) -> ACT in-place
  gemm128ip<64, true>(s.ACT, s.WB0, s.ACT, tid);
  __syncthreads();                      // WB0 reads done, ACT(L3) visible

  copy_w(s.WB0, w4, 192, 0, tid);       // WB0 <- w4 chunk 0
  __syncthreads();

  // L4: 3 l-chunks x 2 row-halves; OUT is 64x64; WB0 holds current chunk
  #pragma unroll
  for (int l = 0; l < 3; l++) {
    // half 0
    gemm64(s.ACT, s.WB0, s.OUT, tid);
    __syncthreads();                    // OUT(h0) ready
    scatter_h(s.OUT, s.htab, s.einfo, l, 0, tid);
    __syncthreads();                    // scatter h0 done (OUT free)
    // half 1
    gemm64(s.ACT + 64 * 68, s.WB0, s.OUT, tid);
    __syncthreads();                    // OUT(h1) ready; all WB0 reads done
    scatter_h(s.OUT, s.htab, s.einfo, l, 1, tid);
    if (l < 2) copy_w(s.WB0, w4, 192, (l + 1) * 64, tid);  // overlap with scatter
    __syncthreads();                    // scatter + copy done
  }
}

// ---------------- per-(node, 2-channel) tensor contraction (symmetrized) --
__global__ void __launch_bounds__(256, 3)
contract_kernel(const int* __restrict__ ai, const float* __restrict__ U1,
                const float* __restrict__ Wc3, const float* __restrict__ Wc2,
                const float* __restrict__ Wc1, int N) {
  __shared__ float4 sU3s[9 * 45];  // [i][pair] x p
  __shared__ float4 sU2s[45];
  __shared__ float4 sU1[9];
  __shared__ float sW3[ZDIM * 4 * CDIM];
  __shared__ float sW2[ZDIM * 4 * CDIM];
  __shared__ float sW1[ZDIM * 4 * CDIM];
  int tid = threadIdx.x;
  for (int i = tid; i < 9 * 45; i += 256) sU3s[i] = ((const float4*)g_U3s)[i];
  if (tid < 45) sU2s[tid] = ((const float4*)g_U2s)[tid];
  if (tid >= 64 && tid < 73) sU1[tid - 64] = ((const float4*)U1)[tid - 64];
  for (int i = tid; i < ZDIM * 64; i += 256) {
    ((float4*)sW3)[i] = ((const float4*)Wc3)[i];
    ((float4*)sW2)[i] = ((const float4*)Wc2)[i];
    ((float4*)sW1)[i] = ((const float4*)Wc1)[i];
  }
  __syncthreads();

  int idx = blockIdx.x * 256 + tid;
  if (idx >= N * 32) return;
  int n = idx >> 5, q = idx & 31, c0 = 2 * q;
  int z = ai[n];

  float xa[9], xb[9];
  const float* mrow = g_msg + n * 576 + c0;
  #pragma unroll
  for (int i = 0; i < 9; i++) {
    float2 v = *reinterpret_cast<const float2*>(mrow + i * 64);
    xa[i] = v.x * (1.0f / 16.0f);
    xb[i] = v.y * (1.0f / 16.0f);
  }

  float2 w3p[4], w2p[4], w1p[4];
  #pragma unroll
  for (int p = 0; p < 4; p++) {
    w3p[p] = *reinterpret_cast<const float2*>(sW3 + z * 256 + p * 64 + c0);
    w2p[p] = *reinterpret_cast<const float2*>(sW2 + z * 256 + p * 64 + c0);
    w1p[p] = *reinterpret_cast<const float2*>(sW1 + z * 256 + p * 64 + c0);
  }

  float resA = 0.f, resB = 0.f;
  int pr = 0;
  for (int j = 0; j < 9; j++) {
    float xja = xa[j], xjb = xb[j];
    for (int k = j; k < 9; k++, pr++) {
      float X2a = xja * xa[k];
      float X2b = xjb * xb[k];
      float a0 = 0.f, a1 = 0.f, a2 = 0.f, a3 = 0.f;
      float b0 = 0.f, b1 = 0.f, b2 = 0.f, b3 = 0.f;
      #pragma unroll
      for (int i = 0; i < 9; i++) {
        float4 u3 = sU3s[i * 45 + pr];
        float xia = xa[i], xib = xb[i];
        a0 = fmaf(u3.x, xia, a0); b0 = fmaf(u3.x, xib, b0);
        a1 = fmaf(u3.y, xia, a1); b1 = fmaf(u3.y, xib, b1);
        a2 = fmaf(u3.z, xia, a2); b2 = fmaf(u3.z, xib, b2);
        a3 = fmaf(u3.w, xia, a3); b3 = fmaf(u3.w, xib, b3);
      }
      float4 u2 = sU2s[pr];
      float ta = u2.x * w2p[0].x + u2.y * w2p[1].x + u2.z * w2p[2].x + u2.w * w2p[3].x;
      float tb = u2.x * w2p[0].y + u2.y * w2p[1].y + u2.z * w2p[2].y + u2.w * w2p[3].y;
      ta = fmaf(a0, w3p[0].x, ta); tb = fmaf(b0, w3p[0].y, tb);
      ta = fmaf(a1, w3p[1].x, ta); tb = fmaf(b1, w3p[1].y, tb);
      ta = fmaf(a2, w3p[2].x, ta); tb = fmaf(b2, w3p[2].y, tb);
      ta = fmaf(a3, w3p[3].x, ta); tb = fmaf(b3, w3p[3].y, tb);
      resA = fmaf(ta, X2a, resA);
      resB = fmaf(tb, X2b, resB);
    }
  }
  #pragma unroll
  for (int j = 0; j < 9; j++) {
    float4 u1 = sU1[j];
    float va = u1.x * w1p[0].x + u1.y * w1p[1].x + u1.z * w1p[2].x + u1.w * w1p[3].x;
    float vb = u1.x * w1p[0].y + u1.y * w1p[1].y + u1.z * w1p[2].y + u1.w * w1p[3].y;
    resA = fmaf(va, xa[j], resA);
    resB = fmaf(vb, xb[j], resB);
  }
  *reinterpret_cast<float2*>(g_xout + n * 64 + c0) = make_float2(resA, resB);
}

// ---------------- final output GEMM: out = xout @ W_out / 8 ----------------
__global__ void __launch_bounds__(256)
out_kernel(const float* __restrict__ W_out, float* __restrict__ out, int N) {
  __shared__ float sW[64 * 64];
  __shared__ float sX[64 * 68];
  int tid = threadIdx.x;
  int n0 = blockIdx.x * 64;
  for (int i = tid; i < 1024; i += 256) ((float4*)sW)[i] = ((const float4*)W_out)[i];
  for (int i = tid; i < 64 * 16; i += 256) {
    int r = i >> 4, c4 = i & 15;
    float4 v = make_float4(0.f, 0.f, 0.f, 0.f);
    if (n0 + r < N) v = *reinterpret_cast<const float4*>(g_xout + (n0 + r) * 64 + c4 * 4);
    *reinterpret_cast<float4*>(sX + r * 68 + c4 * 4) = v;
  }
  __syncthreads();
  int rg = tid >> 4, cg = tid & 15;
  float acc[4][4];
  #pragma unroll
  for (int i = 0; i < 4; i++) { acc[i][0] = 0.f; acc[i][1] = 0.f; acc[i][2] = 0.f; acc[i][3] = 0.f; }
  #pragma unroll 4
  for (int k = 0; k < 64; k++) {
    float4 b = *reinterpret_cast<const float4*>(sW + k * 64 + cg * 4);
    #pragma unroll
    for (int i = 0; i < 4; i++) {
      float a = sX[(rg + 16 * i) * 68 + k];
      acc[i][0] = fmaf(a, b.x, acc[i][0]);
      acc[i][1] = fmaf(a, b.y, acc[i][1]);
      acc[i][2] = fmaf(a, b.z, acc[i][2]);
      acc[i][3] = fmaf(a, b.w, acc[i][3]);
    }
  }
  #pragma unroll
  for (int i = 0; i < 4; i++) {
    int n = n0 + rg + 16 * i;
    if (n < N) {
      *reinterpret_cast<float4*>(out + n * 64 + cg * 4) =
          make_float4(acc[i][0] * 0.125f, acc[i][1] * 0.125f,
                      acc[i][2] * 0.125f, acc[i][3] * 0.125f);
    }
  }
}

// ---------------- launch ----------------
extern "C" void kernel_launch(void* const* d_in, const int* in_sizes, int n_in,
                              void* d_out, int out_size) {
  const float* positions = (const float*)d_in[0];
  const int*   ai        = (const int*)d_in[1];
  const int*   ei        = (const int*)d_in[2];
  const float* W_embed   = (const float*)d_in[3];
  const float* W_up      = (const float*)d_in[4];
  const float* w1        = (const float*)d_in[5];
  const float* w2        = (const float*)d_in[6];
  const float* w3        = (const float*)d_in[7];
  const float* w4        = (const float*)d_in[8];
  const float* U3        = (const float*)d_in[9];
  const float* U2        = (const float*)d_in[10];
  const float* U1        = (const float*)d_in[11];
  const float* Wc3       = (const float*)d_in[12];
  const float* Wc2       = (const float*)d_in[13];
  const float* Wc1       = (const float*)d_in[14];
  const float* W_out     = (const float*)d_in[15];
  float* out = (float*)d_out;

  int N = in_sizes[0] / 3;
  int E = in_sizes[2] / 2;

  cudaFuncSetAttribute(edge_kernel, cudaFuncAttributeMaxDynamicSharedMemorySize,
                       (int)sizeof(ESmem3));

  int msg4 = (N * 576) / 4;
  zero_msg_kernel<<<(msg4 + 255) / 256, 256>>>(msg4);
  htable_kernel<<<1, 640>>>(W_embed, W_up);
  symU_kernel<<<2, 256>>>(U3, U2);
  int ntiles = (E + 127) / 128;
  edge_kernel<<<ntiles, 256, sizeof(ESmem3)>>>(positions, ai, ei, w1, w2, w3, w4, E);
  int nc = N * 32;
  contract_kernel<<<(nc + 255) / 256, 256>>>(ai, U1, Wc3, Wc2, Wc1, N);
  out_kernel<<<(N + 63) / 64, 256>>>(W_out, out, N);

  (void)n_in; (void)out_size;
}